// round 17
// baseline (speedup 1.0000x reference)
#include <cuda_runtime.h>
#include <cuda_fp16.h>
#include <cuda_bf16.h>
#include <cstdint>

#define INPUT_DIM 16384
#define EMB 1024
#define BATCH 4096
#define XS_H (INPUT_DIM + EMB * 7)   // 23552 halves, pad-8 bound (<32768, fits 15 bits)

#define GTHREADS 512
#define GRID_G   296                 // 2 CTAs/SM x 148 SMs, single persistent wave

// ---------------- device scratch ----------------
__device__ unsigned short g_comb[INPUT_DIM];                 // e | (neg<<15) per feature j
__device__ __align__(16) unsigned short g_pos[INPUT_DIM];    // slot | (neg<<15), by j
__device__ int g_astart[EMB];                                // pad-8 bucket start (half units)
__device__ int g_len[EMB];                                   // actual bucket length

// ---------------- K1: extract (champion: 1 row/warp, 2-round batched prefetch) ----------------
__global__ void k_extract(const float* __restrict__ hp) {
    int warp = (blockIdx.x * blockDim.x + threadIdx.x) >> 5;
    int lane = threadIdx.x & 31;
    if (warp >= INPUT_DIM) return;

    const float4* row = reinterpret_cast<const float4*>(hp + (size_t)warp * EMB);
    float4 c[4];
    int my_e = 0; unsigned my_neg = 0; bool has = false;

#pragma unroll
    for (int i = 0; i < 4; i++) c[i] = row[lane + i * 32];
#pragma unroll
    for (int i = 0; i < 4; i++) {
        int base = (lane + i * 32) * 4;
        if (c[i].x != 0.0f) { my_e = base + 0; my_neg = (c[i].x < 0.0f); has = true; }
        if (c[i].y != 0.0f) { my_e = base + 1; my_neg = (c[i].y < 0.0f); has = true; }
        if (c[i].z != 0.0f) { my_e = base + 2; my_neg = (c[i].z < 0.0f); has = true; }
        if (c[i].w != 0.0f) { my_e = base + 3; my_neg = (c[i].w < 0.0f); has = true; }
    }
    unsigned mask = __ballot_sync(0xffffffffu, has);

    if (mask == 0) {
#pragma unroll
        for (int i = 0; i < 4; i++) c[i] = row[lane + (i + 4) * 32];
#pragma unroll
        for (int i = 0; i < 4; i++) {
            int base = (lane + (i + 4) * 32) * 4;
            if (c[i].x != 0.0f) { my_e = base + 0; my_neg = (c[i].x < 0.0f); has = true; }
            if (c[i].y != 0.0f) { my_e = base + 1; my_neg = (c[i].y < 0.0f); has = true; }
            if (c[i].z != 0.0f) { my_e = base + 2; my_neg = (c[i].z < 0.0f); has = true; }
            if (c[i].w != 0.0f) { my_e = base + 3; my_neg = (c[i].w < 0.0f); has = true; }
        }
        mask = __ballot_sync(0xffffffffu, has);
    }

    if (mask == 0) { if (lane == 0) g_comb[warp] = 0; return; }
    int src = __ffs(mask) - 1;
    int e        = __shfl_sync(0xffffffffu, my_e, src);
    unsigned neg = __shfl_sync(0xffffffffu, my_neg, src);
    if (lane == 0) g_comb[warp] = (unsigned short)(e | (neg << 15));
}

// ---------------- K2: build (pad-8 for 16B-aligned fp16 reduce) ----------------
__global__ __launch_bounds__(EMB, 1)
void k_build() {
    __shared__ int hist[EMB];
    __shared__ int cur[EMB];
    __shared__ int wsum[32];
    int t = threadIdx.x;
    int lane = t & 31, w = t >> 5;

    hist[t] = 0;
    __syncthreads();

#pragma unroll
    for (int i = 0; i < INPUT_DIM / EMB; i++)
        atomicAdd(&hist[g_comb[i * EMB + t] & (EMB - 1)], 1);
    __syncthreads();

    int c  = hist[t];
    int pl = (c + 7) & ~7;                 // pad to 8 halves (16B alignment)

    int v = pl;
#pragma unroll
    for (int off = 1; off < 32; off <<= 1) {
        int n = __shfl_up_sync(0xffffffffu, v, off);
        if (lane >= off) v += n;
    }
    if (lane == 31) wsum[w] = v;
    __syncthreads();
    if (w == 0) {
        int s = wsum[lane];
#pragma unroll
        for (int off = 1; off < 32; off <<= 1) {
            int n = __shfl_up_sync(0xffffffffu, s, off);
            if (lane >= off) s += n;
        }
        wsum[lane] = s;
    }
    __syncthreads();
    int incl  = v + (w > 0 ? wsum[w - 1] : 0);
    int start = incl - pl;
    g_astart[t] = start;
    g_len[t]    = c;
    cur[t]      = start;
    __syncthreads();

#pragma unroll
    for (int i = 0; i < INPUT_DIM / EMB; i++) {
        int j = i * EMB + t;
        unsigned cb = g_comb[j];
        int pos = atomicAdd(&cur[cb & (EMB - 1)], 1);
        g_pos[j] = (unsigned short)(pos | (cb & 0x8000u));
    }
}

// ---------------- K3: persistent gather — fp16 scatter stage, fp32 accumulation ----------------
__global__ __launch_bounds__(GTHREADS, 2)
void k_gather(const float* __restrict__ x, float* __restrict__ out) {
    extern __shared__ unsigned short xsh[];    // [XS_H] fp16 bits, sign pre-applied
    int t = threadIdx.x;

    int s0a = __ldg(&g_astart[t]);
    int la  = __ldg(&g_len[t]);
    int s0b = __ldg(&g_astart[t + GTHREADS]);
    int lb  = __ldg(&g_len[t + GTHREADS]);

    uint2 q[8];
    {
        const uint2* gp = reinterpret_cast<const uint2*>(g_pos);
#pragma unroll
        for (int i = 0; i < 8; i++) q[i] = gp[t + i * GTHREADS];
    }

    // zero pad slots once (<=7 per bucket; scatter never writes pads)
    {
        int pa = (la + 7) & ~7;
        for (int k = s0a + la; k < s0a + pa; k++) xsh[k] = 0;
        int pb = (lb + 7) & ~7;
        for (int k = s0b + lb; k < s0b + pb; k++) xsh[k] = 0;
    }

    int n8a = ((la + 7) & ~7) >> 3;
    int n8b = ((lb + 7) & ~7) >> 3;

    // first-row prefetch (both halves)
    int b = blockIdx.x;
    float4 vlo[4], vhi[4];
    if (b < BATCH) {
        const float4* gx = reinterpret_cast<const float4*>(x + (size_t)b * INPUT_DIM);
#pragma unroll
        for (int i = 0; i < 4; i++) vlo[i] = gx[t + i * GTHREADS];
#pragma unroll
        for (int i = 0; i < 4; i++) vhi[i] = gx[t + (i + 4) * GTHREADS];
    }

    for (; b < BATCH; b += GRID_G) {
        __syncthreads();                   // pads ready / prev reduce done reading xsh
        int bn = b + GRID_G;
        const float4* gxn = reinterpret_cast<const float4*>(x + (size_t)bn * INPUT_DIM);

        // scatter lo half (fp32 -> fp16, sign = bit15 of pos entry), then refill lo
#pragma unroll
        for (int i = 0; i < 4; i++) {
            unsigned q0 = q[i].x & 0xFFFFu, q1 = q[i].x >> 16;
            unsigned q2 = q[i].y & 0xFFFFu, q3 = q[i].y >> 16;
            xsh[q0 & 0x7FFFu] = (unsigned short)(__half_as_ushort(__float2half_rn(vlo[i].x)) ^ (q0 & 0x8000u));
            xsh[q1 & 0x7FFFu] = (unsigned short)(__half_as_ushort(__float2half_rn(vlo[i].y)) ^ (q1 & 0x8000u));
            xsh[q2 & 0x7FFFu] = (unsigned short)(__half_as_ushort(__float2half_rn(vlo[i].z)) ^ (q2 & 0x8000u));
            xsh[q3 & 0x7FFFu] = (unsigned short)(__half_as_ushort(__float2half_rn(vlo[i].w)) ^ (q3 & 0x8000u));
        }
        if (bn < BATCH) {
#pragma unroll
            for (int i = 0; i < 4; i++) vlo[i] = gxn[t + i * GTHREADS];
        }

        // scatter hi half, then refill hi
#pragma unroll
        for (int i = 0; i < 4; i++) {
            unsigned q0 = q[i + 4].x & 0xFFFFu, q1 = q[i + 4].x >> 16;
            unsigned q2 = q[i + 4].y & 0xFFFFu, q3 = q[i + 4].y >> 16;
            xsh[q0 & 0x7FFFu] = (unsigned short)(__half_as_ushort(__float2half_rn(vhi[i].x)) ^ (q0 & 0x8000u));
            xsh[q1 & 0x7FFFu] = (unsigned short)(__half_as_ushort(__float2half_rn(vhi[i].y)) ^ (q1 & 0x8000u));
            xsh[q2 & 0x7FFFu] = (unsigned short)(__half_as_ushort(__float2half_rn(vhi[i].z)) ^ (q2 & 0x8000u));
            xsh[q3 & 0x7FFFu] = (unsigned short)(__half_as_ushort(__float2half_rn(vhi[i].w)) ^ (q3 & 0x8000u));
        }
        if (bn < BATCH) {
#pragma unroll
            for (int i = 0; i < 4; i++) vhi[i] = gxn[t + (i + 4) * GTHREADS];
        }

        __syncthreads();                   // scatter visible

        // reduce: 16B = 8 halves per LDS.128; accumulate in fp32
        float* o = out + (size_t)b * EMB;
        {
            const uint4* p = reinterpret_cast<const uint4*>(xsh) + (s0a >> 3);
            float acc = 0.0f;
            for (int i = 0; i < n8a; i++) {
                uint4 u = p[i];
                float2 f0 = __half22float2(*reinterpret_cast<const __half2*>(&u.x));
                float2 f1 = __half22float2(*reinterpret_cast<const __half2*>(&u.y));
                float2 f2 = __half22float2(*reinterpret_cast<const __half2*>(&u.z));
                float2 f3 = __half22float2(*reinterpret_cast<const __half2*>(&u.w));
                acc += ((f0.x + f0.y) + (f1.x + f1.y)) + ((f2.x + f2.y) + (f3.x + f3.y));
            }
            o[t] = acc;
        }
        {
            const uint4* p = reinterpret_cast<const uint4*>(xsh) + (s0b >> 3);
            float acc = 0.0f;
            for (int i = 0; i < n8b; i++) {
                uint4 u = p[i];
                float2 f0 = __half22float2(*reinterpret_cast<const __half2*>(&u.x));
                float2 f1 = __half22float2(*reinterpret_cast<const __half2*>(&u.y));
                float2 f2 = __half22float2(*reinterpret_cast<const __half2*>(&u.z));
                float2 f3 = __half22float2(*reinterpret_cast<const __half2*>(&u.w));
                acc += ((f0.x + f0.y) + (f1.x + f1.y)) + ((f2.x + f2.y) + (f3.x + f3.y));
            }
            o[t + GTHREADS] = acc;
        }
    }
}

extern "C" void kernel_launch(void* const* d_in, const int* in_sizes, int n_in,
                              void* d_out, int out_size) {
    const float* x  = (const float*)d_in[0];   // [BATCH, INPUT_DIM]
    const float* hp = (const float*)d_in[1];   // [INPUT_DIM, EMB]
    float* out = (float*)d_out;                // [BATCH, EMB]

    int smem = XS_H * (int)sizeof(unsigned short);  // 47104 B -> 2 blocks/SM (reg-limited)
    cudaFuncSetAttribute(k_gather, cudaFuncAttributeMaxDynamicSharedMemorySize, smem);

    k_extract<<<(INPUT_DIM * 32) / 256, 256>>>(hp);
    k_build<<<1, EMB>>>();
    k_gather<<<GRID_G, GTHREADS, smem>>>(x, out);
}